// round 16
// baseline (speedup 1.0000x reference)
#include <cuda_runtime.h>
#include <cuda_fp16.h>
#include <math.h>
#include <stdint.h>

#define SEQ    2048
#define DMODEL 2048
#define NH     16
#define DH     128
#define QKV_N  6144
#define NQB    (SEQ / 128)              // 16 q-tiles
#define MAXSPL 8
#define NITEMS 72                       // sum of ns(qb) = (2qb+5)/4 over qb=0..15

// ---------------------------------------------------------------------------
// Scratch (__device__ globals; allocation-free rule)
// ---------------------------------------------------------------------------
__device__ __align__(16) __half g_xh[SEQ * DMODEL];
__device__ __align__(16) __half g_wqkvh[(size_t)DMODEL * QKV_N];   // [K][N] fp16
__device__ __align__(16) __half g_wouth[(size_t)DMODEL * DMODEL];  // [K][N] fp16
__device__ __align__(16) __half g_qkv[(size_t)SEQ * QKV_N];
__device__ __align__(16) __half g_attn[SEQ * DMODEL];
__device__ __align__(16) __half g_opart[(size_t)MAXSPL * SEQ * DMODEL]; // normalized fp16 partials
__device__ __align__(16) float  g_oml[MAXSPL * SEQ * NH * 2];           // (m, l)

// ---------------------------------------------------------------------------
// PTX helpers
// ---------------------------------------------------------------------------
__device__ __forceinline__ uint32_t smem_u32(const void* p) {
    uint32_t a;
    asm("{ .reg .u64 t; cvta.to.shared.u64 t, %1; cvt.u32.u64 %0, t; }"
        : "=r"(a) : "l"(p));
    return a;
}
__device__ __forceinline__ void ldmx4(uint32_t r[4], uint32_t addr) {
    asm volatile("ldmatrix.sync.aligned.m8n8.x4.shared.b16 {%0,%1,%2,%3}, [%4];"
                 : "=r"(r[0]), "=r"(r[1]), "=r"(r[2]), "=r"(r[3]) : "r"(addr));
}
__device__ __forceinline__ void ldmx4t(uint32_t r[4], uint32_t addr) {
    asm volatile("ldmatrix.sync.aligned.m8n8.x4.trans.shared.b16 {%0,%1,%2,%3}, [%4];"
                 : "=r"(r[0]), "=r"(r[1]), "=r"(r[2]), "=r"(r[3]) : "r"(addr));
}
__device__ __forceinline__ void mma_f16(float c[4], const uint32_t a[4],
                                        uint32_t b0, uint32_t b1) {
    asm volatile(
        "mma.sync.aligned.m16n8k16.row.col.f32.f16.f16.f32 "
        "{%0,%1,%2,%3}, {%4,%5,%6,%7}, {%8,%9}, {%0,%1,%2,%3};"
        : "+f"(c[0]), "+f"(c[1]), "+f"(c[2]), "+f"(c[3])
        : "r"(a[0]), "r"(a[1]), "r"(a[2]), "r"(a[3]), "r"(b0), "r"(b1));
}
__device__ __forceinline__ void cp16(uint32_t dst, const void* src) {
    asm volatile("cp.async.cg.shared.global [%0], [%1], 16;" :: "r"(dst), "l"(src));
}
#define CP_COMMIT() asm volatile("cp.async.commit_group;" ::: "memory")
#define CP_WAIT0()  asm volatile("cp.async.wait_group 0;" ::: "memory")
#define CP_WAIT1()  asm volatile("cp.async.wait_group 1;" ::: "memory")

__device__ __forceinline__ uint32_t packh2(float a, float b) {
    __half2 h = __floats2half2_rn(a, b);
    return *reinterpret_cast<uint32_t*>(&h);
}

// ---------------------------------------------------------------------------
// Fused prepass: fp32 -> fp16 for x, Wqkv, out_w.
// Grid-stride, 32 float4 per thread (unroll 4 -> MLP_eff ~4).
// 640 CTAs x 256 thr x 32 iters = 5,242,880 float4 = exactly S0+S1+S2 floats.
// ---------------------------------------------------------------------------
#define S0 ((size_t)SEQ * DMODEL)
#define S1 ((size_t)DMODEL * QKV_N)
#define S2 ((size_t)DMODEL * DMODEL)
#define CVT_THREADS_TOT (640 * 256)     // 163840
#define CVT_ITERS 32

__global__ void cvt_all(const float* __restrict__ x, const float* __restrict__ w1,
                        const float* __restrict__ w2,
                        __half* __restrict__ xh, __half* __restrict__ w1h,
                        __half* __restrict__ w2h) {
    const size_t gtid = (size_t)blockIdx.x * 256 + threadIdx.x;
    #pragma unroll 4
    for (int it = 0; it < CVT_ITERS; it++) {
        size_t i = ((size_t)it * CVT_THREADS_TOT + gtid) * 4;
        const float* src; __half* dst; size_t off;
        if (i < S0)           { src = x;  dst = xh;  off = i; }
        else if (i < S0 + S1) { src = w1; dst = w1h; off = i - S0; }
        else                  { src = w2; dst = w2h; off = i - S0 - S1; }
        float4 v = *reinterpret_cast<const float4*>(src + off);
        uint2 o;
        o.x = packh2(v.x, v.y);
        o.y = packh2(v.z, v.w);
        *reinterpret_cast<uint2*>(dst + off) = o;
    }
}

// ---------------------------------------------------------------------------
// fp16 tensor GEMM (R12 winner): C[M,N] = A[M,K] @ B[K,N] + bias (B row-major)
// 256x128 CTA tile, BK=64, 512 threads (16 warps: 8m x 2n), warp tile 32x64.
// 3-stage cp.async pipeline (prefetch distance 2), one __syncthreads per tile.
// ---------------------------------------------------------------------------
#define BKH 64
#define A_PITCH_B 144
#define B_PITCH_B 272
#define A_TILE_B (256 * A_PITCH_B)      // 36864
#define B_TILE_B (64 * B_PITCH_B)       // 17408
#define STG_B (A_TILE_B + B_TILE_B)     // 54272
#define GEMM_SMEM (3 * STG_B)           // 162816

__global__ __launch_bounds__(512, 1) void gemm_h(
    const __half* __restrict__ A, const __half* __restrict__ B,
    const float* __restrict__ bias, __half* __restrict__ Ch,
    float* __restrict__ Cf, int M, int N, int K)
{
    extern __shared__ char sh[];
    const uint32_t sbase = smem_u32(sh);

    const int tid  = threadIdx.x;
    const int warp = tid >> 5;
    const int lane = tid & 31;
    const int gq   = lane >> 2;
    const int kq   = lane & 3;
    const int wm   = warp >> 1;
    const int wn   = warp & 1;
    const int row0 = blockIdx.y * 256;
    const int col0 = blockIdx.x * 128;
    const int ntiles = K / BKH;

    const int lrA = tid >> 1;
    const int lbA = (tid & 1) * 64;
    const __half* gA = A + (size_t)(row0 + lrA) * K + (lbA >> 1);
    const int brB = tid >> 3;
    const int bcB = (tid & 7) * 32;
    const __half* gB = B + (size_t)brB * N + col0 + (bcB >> 1);

    const uint32_t aRel = (uint32_t)((wm * 32 + (lane & 15)) * A_PITCH_B
                                     + (lane >> 4) * 16);
    const uint32_t bRel = (uint32_t)A_TILE_B
        + (uint32_t)(((lane & 7) + ((lane >> 3) & 1) * 8) * B_PITCH_B
                     + ((lane >> 4) & 1) * 16 + wn * 128);

    float acc[2][8][4];
    #pragma unroll
    for (int mt = 0; mt < 2; mt++)
        #pragma unroll
        for (int nt = 0; nt < 8; nt++)
            #pragma unroll
            for (int i = 0; i < 4; i++) acc[mt][nt][i] = 0.f;

    #define LOAD_TILE(t, s) do {                                                \
        uint32_t base_ = sbase + (uint32_t)(s) * STG_B;                         \
        const __half* a_ = gA + (size_t)(t) * BKH;                              \
        uint32_t da_ = base_ + (uint32_t)(lrA * A_PITCH_B + lbA);               \
        cp16(da_,      a_);      cp16(da_ + 16, a_ + 8);                        \
        cp16(da_ + 32, a_ + 16); cp16(da_ + 48, a_ + 24);                       \
        const __half* b_ = gB + (size_t)(t) * BKH * N;                          \
        uint32_t db_ = base_ + A_TILE_B + (uint32_t)(brB * B_PITCH_B + bcB);    \
        cp16(db_, b_); cp16(db_ + 16, b_ + 8);                                  \
        CP_COMMIT();                                                            \
    } while (0)

    #define COMPUTE(s) do {                                                     \
        uint32_t ab_ = sbase + (uint32_t)(s) * STG_B + aRel;                    \
        uint32_t bb_ = sbase + (uint32_t)(s) * STG_B + bRel;                    \
        _Pragma("unroll")                                                       \
        for (int ks = 0; ks < 4; ks++) {                                        \
            uint32_t af0[4], af1[4];                                            \
            ldmx4(af0, ab_ + ks * 32);                                          \
            ldmx4(af1, ab_ + 16 * A_PITCH_B + ks * 32);                         \
            _Pragma("unroll")                                                   \
            for (int p = 0; p < 4; p++) {                                       \
                uint32_t bf[4];                                                 \
                ldmx4t(bf, bb_ + ks * (16 * B_PITCH_B) + p * 32);               \
                mma_f16(acc[0][2 * p],     af0, bf[0], bf[1]);                  \
                mma_f16(acc[0][2 * p + 1], af0, bf[2], bf[3]);                  \
                mma_f16(acc[1][2 * p],     af1, bf[0], bf[1]);                  \
                mma_f16(acc[1][2 * p + 1], af1, bf[2], bf[3]);                  \
            }                                                                   \
        }                                                                       \
    } while (0)

    LOAD_TILE(0, 0);
    LOAD_TILE(1, 1);
    for (int t = 0; t < ntiles; t++) {
        if (t + 1 < ntiles) CP_WAIT1(); else CP_WAIT0();
        __syncthreads();
        if (t + 2 < ntiles) {
            int s2 = (t + 2) % 3;
            LOAD_TILE(t + 2, s2);
        }
        COMPUTE(t % 3);
    }

    #pragma unroll
    for (int mt = 0; mt < 2; mt++) {
        int r = row0 + wm * 32 + mt * 16 + gq;
        #pragma unroll
        for (int nt = 0; nt < 8; nt++) {
            int c = col0 + wn * 64 + nt * 8 + kq * 2;
            float b0 = bias[c], b1 = bias[c + 1];
            float v0 = acc[mt][nt][0] + b0, v1 = acc[mt][nt][1] + b1;
            float v2 = acc[mt][nt][2] + b0, v3 = acc[mt][nt][3] + b1;
            if (Ch) {
                *reinterpret_cast<uint32_t*>(&Ch[(size_t)r * N + c]) = packh2(v0, v1);
                *reinterpret_cast<uint32_t*>(&Ch[(size_t)(r + 8) * N + c]) = packh2(v2, v3);
            } else {
                *reinterpret_cast<float2*>(&Cf[(size_t)r * N + c]) = make_float2(v0, v1);
                *reinterpret_cast<float2*>(&Cf[(size_t)(r + 8) * N + c]) = make_float2(v2, v3);
            }
        }
    }
}

// ---------------------------------------------------------------------------
// Variable split-KV flash attention, chunk = 4 key-blocks per CTA (R14 exact).
// ns==1 (qb<=1): writes final normalized output DIRECTLY to attn.
// ns>1: writes NORMALIZED fp16 partial O + (m, l) fp32; combineN merges.
// ---------------------------------------------------------------------------
#define FROW_B 272
#define QTILE_B (128 * FROW_B)          // 34816
#define KTILE_B (64 * FROW_B)           // 17408
#define KVSTG_B (2 * KTILE_B)           // 34816
#define FLASH_SMEM (QTILE_B + 2 * KVSTG_B)  // 104448

__global__ __launch_bounds__(256, 2) void flash_split(
    const __half* __restrict__ qkv, const float* __restrict__ attn_bias,
    __half* __restrict__ Opart, float* __restrict__ Oml,
    __half* __restrict__ attn)
{
    extern __shared__ char fsm[];
    const uint32_t qsb  = smem_u32(fsm);
    const uint32_t kvsb = qsb + QTILE_B;

    // item -> (qb, split), heavy-first (qb 15 down)
    int item = blockIdx.x;
    int qb = NQB - 1, split = 0;
    #pragma unroll
    for (int it = 0; it < NQB; it++) {
        int ns_ = (2 * qb + 5) >> 2;
        if (item < ns_) { split = item; break; }
        item -= ns_; qb--;
    }
    const int ns  = (2 * qb + 5) >> 2;

    const int nb  = 2 * qb + 2;                // total causal key blocks
    const int kb0 = split * 4;
    int kend = kb0 + 4; if (kend > nb) kend = nb;
    const int nkb = kend - kb0;

    const int h    = blockIdx.y;
    const int tid  = threadIdx.x;
    const int warp = tid >> 5;
    const int lane = tid & 31;
    const int gq   = lane >> 2;
    const int kq   = lane & 3;

    const float scale = 0.08838834764831845f;  // 1/sqrt(128)
    const float* bh = attn_bias + (size_t)h * SEQ;

    const uint32_t qOff = qsb + (uint32_t)((warp * 16 + (lane & 15)) * FROW_B
                                           + (lane >> 4) * 16);
    const int kRow = (lane & 7) + ((lane >> 4) & 1) * 8;
    const uint32_t kRel = (uint32_t)(kRow * FROW_B + ((lane >> 3) & 1) * 16);
    const int vRow = (lane & 7) + ((lane >> 3) & 1) * 8;
    const uint32_t vRel = (uint32_t)(vRow * FROW_B + ((lane >> 4) & 1) * 16) + KTILE_B;

    #define LOADKV(kbg_, s_) do {                                               \
        uint32_t kvb_ = kvsb + (uint32_t)(s_) * KVSTG_B;                        \
        _Pragma("unroll")                                                       \
        for (int i_ = 0; i_ < 4; i_++) {                                        \
            int idx_ = tid + i_ * 256;                                          \
            int r_ = idx_ >> 4, c_ = idx_ & 15;                                 \
            const __half* kp_ = &qkv[(size_t)((kbg_) * 64 + r_) * QKV_N         \
                                     + DMODEL + h * DH + c_ * 8];               \
            uint32_t d_ = kvb_ + (uint32_t)(r_ * FROW_B + c_ * 16);             \
            cp16(d_, kp_);                                                      \
            cp16(d_ + KTILE_B, kp_ + DMODEL);                                   \
        }                                                                       \
        CP_COMMIT();                                                            \
    } while (0)

    // ---- prologue: Q tile + first K/V block ----
    #pragma unroll
    for (int i = 0; i < 8; i++) {
        int idx = tid + i * 256;
        int r = idx >> 4, c = idx & 15;
        cp16(qsb + (uint32_t)(r * FROW_B + c * 16),
             &qkv[(size_t)(qb * 128 + r) * QKV_N + h * DH + c * 8]);
    }
    LOADKV(kb0, 0);

    float o[16][4];
    #pragma unroll
    for (int nt = 0; nt < 16; nt++)
        #pragma unroll
        for (int i = 0; i < 4; i++) o[nt][i] = 0.f;
    float m0 = -1e30f, m1 = -1e30f, l0 = 0.f, l1 = 0.f;

    const int qrow0 = qb * 128 + warp * 16 + gq;

    for (int kb = 0; kb < nkb; kb++) {
        const int kbg = kb0 + kb;
        CP_WAIT0();
        __syncthreads();
        if (kb + 1 < nkb) LOADKV(kb0 + kb + 1, (kb + 1) & 1);

        const uint32_t stg = kvsb + (uint32_t)(kb & 1) * KVSTG_B;
        const uint32_t kOff = stg + kRel;
        const uint32_t vOff = stg + vRel;

        // ---- S(16x64) = Q @ K^T ----
        float s[8][4];
        #pragma unroll
        for (int nt = 0; nt < 8; nt++)
            #pragma unroll
            for (int i = 0; i < 4; i++) s[nt][i] = 0.f;

        #pragma unroll
        for (int ks = 0; ks < 8; ks++) {
            uint32_t aq[4];
            ldmx4(aq, qOff + ks * 32);
            #pragma unroll
            for (int p = 0; p < 4; p++) {
                uint32_t bf[4];
                ldmx4(bf, kOff + p * (16 * FROW_B) + ks * 32);
                mma_f16(s[2 * p],     aq, bf[0], bf[1]);
                mma_f16(s[2 * p + 1], aq, bf[2], bf[3]);
            }
        }

        // ---- bias + scale + causal mask ----
        const bool diag = (kbg >= 2 * qb);
        #pragma unroll
        for (int nt = 0; nt < 8; nt++) {
            int j = nt * 8 + kq * 2;
            float b0v = bh[kbg * 64 + j], b1v = bh[kbg * 64 + j + 1];
            s[nt][0] = s[nt][0] * scale + b0v;
            s[nt][1] = s[nt][1] * scale + b1v;
            s[nt][2] = s[nt][2] * scale + b0v;
            s[nt][3] = s[nt][3] * scale + b1v;
            if (diag) {
                int jg = kbg * 64 + j;
                if (jg     > qrow0)     s[nt][0] = -1e30f;
                if (jg + 1 > qrow0)     s[nt][1] = -1e30f;
                if (jg     > qrow0 + 8) s[nt][2] = -1e30f;
                if (jg + 1 > qrow0 + 8) s[nt][3] = -1e30f;
            }
        }

        // ---- online softmax (guarded exp: all-masked rows stay zero) ----
        float mx0 = -1e30f, mx1 = -1e30f;
        #pragma unroll
        for (int nt = 0; nt < 8; nt++) {
            mx0 = fmaxf(mx0, fmaxf(s[nt][0], s[nt][1]));
            mx1 = fmaxf(mx1, fmaxf(s[nt][2], s[nt][3]));
        }
        mx0 = fmaxf(mx0, __shfl_xor_sync(0xffffffffu, mx0, 1));
        mx0 = fmaxf(mx0, __shfl_xor_sync(0xffffffffu, mx0, 2));
        mx1 = fmaxf(mx1, __shfl_xor_sync(0xffffffffu, mx1, 1));
        mx1 = fmaxf(mx1, __shfl_xor_sync(0xffffffffu, mx1, 2));

        float mn0 = fmaxf(m0, mx0), mn1 = fmaxf(m1, mx1);
        float al0 = __expf(m0 - mn0), al1 = __expf(m1 - mn1);
        m0 = mn0; m1 = mn1;

        float ps0 = 0.f, ps1 = 0.f;
        #pragma unroll
        for (int nt = 0; nt < 8; nt++) {
            s[nt][0] = (s[nt][0] > -1e29f) ? __expf(s[nt][0] - mn0) : 0.f;
            s[nt][1] = (s[nt][1] > -1e29f) ? __expf(s[nt][1] - mn0) : 0.f;
            s[nt][2] = (s[nt][2] > -1e29f) ? __expf(s[nt][2] - mn1) : 0.f;
            s[nt][3] = (s[nt][3] > -1e29f) ? __expf(s[nt][3] - mn1) : 0.f;
            ps0 += s[nt][0] + s[nt][1];
            ps1 += s[nt][2] + s[nt][3];
        }
        ps0 += __shfl_xor_sync(0xffffffffu, ps0, 1);
        ps0 += __shfl_xor_sync(0xffffffffu, ps0, 2);
        ps1 += __shfl_xor_sync(0xffffffffu, ps1, 1);
        ps1 += __shfl_xor_sync(0xffffffffu, ps1, 2);
        l0 = l0 * al0 + ps0;
        l1 = l1 * al1 + ps1;

        #pragma unroll
        for (int nt = 0; nt < 16; nt++) {
            o[nt][0] *= al0; o[nt][1] *= al0;
            o[nt][2] *= al1; o[nt][3] *= al1;
        }

        // ---- O += P @ V (P straight from registers) ----
        #pragma unroll
        for (int ks = 0; ks < 4; ks++) {
            uint32_t ap[4];
            ap[0] = packh2(s[2 * ks][0],     s[2 * ks][1]);
            ap[1] = packh2(s[2 * ks][2],     s[2 * ks][3]);
            ap[2] = packh2(s[2 * ks + 1][0], s[2 * ks + 1][1]);
            ap[3] = packh2(s[2 * ks + 1][2], s[2 * ks + 1][3]);
            #pragma unroll
            for (int p = 0; p < 8; p++) {
                uint32_t bf[4];
                ldmx4t(bf, vOff + ks * (16 * FROW_B) + p * 32);
                mma_f16(o[2 * p],     ap, bf[0], bf[1]);
                mma_f16(o[2 * p + 1], ap, bf[2], bf[3]);
            }
        }
    }

    // ---- epilogue: normalized fp16; direct to attn when ns==1 ----
    float il0 = (l0 > 0.f) ? 1.f / l0 : 0.f;
    float il1 = (l1 > 0.f) ? 1.f / l1 : 0.f;
    int r = qrow0;
    __half* op = (ns == 1)
        ? attn  + (size_t)r * DMODEL + h * DH
        : Opart + (size_t)(split * SEQ + r) * DMODEL + h * DH;
    #pragma unroll
    for (int nt = 0; nt < 16; nt++) {
        int col = nt * 8 + kq * 2;
        *reinterpret_cast<uint32_t*>(op + col) =
            packh2(o[nt][0] * il0, o[nt][1] * il0);
        *reinterpret_cast<uint32_t*>(op + 8 * DMODEL + col) =
            packh2(o[nt][2] * il1, o[nt][3] * il1);
    }
    if (ns > 1 && kq == 0) {
        float* ml = Oml + ((size_t)(split * SEQ + r) * NH + h) * 2;
        ml[0] = m0; ml[1] = l0;
        float* ml8 = Oml + ((size_t)(split * SEQ + r + 8) * NH + h) * 2;
        ml8[0] = m1; ml8[1] = l1;
    }
}

// ---------------------------------------------------------------------------
// Combine ns(qb) normalized fp16 partials -> fp16 attn (skips ns==1 rows).
// (m,l) staged in smem once per block.
// ---------------------------------------------------------------------------
__global__ void combineN(const __half* __restrict__ Opart,
                         const float* __restrict__ Oml,
                         __half* __restrict__ attn)
{
    __shared__ float2 sml[MAXSPL][NH];

    int r = blockIdx.x + 256;           // rows 0..255 (qb 0,1) handled by flash
    int t = threadIdx.x;
    int c0 = t * 8;
    int h = c0 >> 7;
    int qb = r >> 7;
    int ns = (2 * qb + 5) >> 2;

    if (t < ns * NH) {
        int s = t >> 4, hh = t & 15;
        sml[s][hh] = *reinterpret_cast<const float2*>(
            Oml + ((size_t)(s * SEQ + r) * NH + hh) * 2);
    }
    __syncthreads();

    float m = -1e30f;
    #pragma unroll
    for (int s = 0; s < MAXSPL; s++) {
        if (s >= ns) break;
        m = fmaxf(m, sml[s][h].x);
    }
    float L = 0.f;
    float al[MAXSPL];
    #pragma unroll
    for (int s = 0; s < MAXSPL; s++) {
        if (s >= ns) break;
        al[s] = sml[s][h].y * __expf(sml[s][h].x - m);
        L += al[s];
    }
    float inv = 1.f / L;

    float a[8] = {0.f, 0.f, 0.f, 0.f, 0.f, 0.f, 0.f, 0.f};
    #pragma unroll
    for (int s = 0; s < MAXSPL; s++) {
        if (s >= ns) break;
        float w = al[s];
        const __half* p = Opart + (size_t)(s * SEQ + r) * DMODEL + c0;
        uint4 v = *reinterpret_cast<const uint4*>(p);
        const __half2* h2 = reinterpret_cast<const __half2*>(&v);
        #pragma unroll
        for (int q = 0; q < 4; q++) {
            float2 f = __half22float2(h2[q]);
            a[2 * q]     += w * f.x;
            a[2 * q + 1] += w * f.y;
        }
    }

    uint4 outv;
    outv.x = packh2(a[0] * inv, a[1] * inv);
    outv.y = packh2(a[2] * inv, a[3] * inv);
    outv.z = packh2(a[4] * inv, a[5] * inv);
    outv.w = packh2(a[6] * inv, a[7] * inv);
    *reinterpret_cast<uint4*>(attn + (size_t)r * DMODEL + c0) = outv;
}

// ---------------------------------------------------------------------------
// kernel_launch
// ---------------------------------------------------------------------------
extern "C" void kernel_launch(void* const* d_in, const int* in_sizes, int n_in,
                              void* d_out, int out_size)
{
    (void)in_sizes; (void)n_in; (void)out_size;
    const float* x         = (const float*)d_in[0];
    const float* Wqkv      = (const float*)d_in[1];
    const float* Wqkv_bias = (const float*)d_in[2];
    const float* out_w     = (const float*)d_in[3];
    const float* out_b     = (const float*)d_in[4];
    const float* attn_bias = (const float*)d_in[5];
    float* out = (float*)d_out;

    __half *xh, *wqkvh, *wouth, *qkv, *attn, *opart;
    float *oml;
    cudaGetSymbolAddress((void**)&xh,    g_xh);
    cudaGetSymbolAddress((void**)&wqkvh, g_wqkvh);
    cudaGetSymbolAddress((void**)&wouth, g_wouth);
    cudaGetSymbolAddress((void**)&qkv,   g_qkv);
    cudaGetSymbolAddress((void**)&attn,  g_attn);
    cudaGetSymbolAddress((void**)&opart, g_opart);
    cudaGetSymbolAddress((void**)&oml,   g_oml);

    cudaFuncSetAttribute(gemm_h, cudaFuncAttributeMaxDynamicSharedMemorySize,
                         GEMM_SMEM);
    cudaFuncSetAttribute(flash_split, cudaFuncAttributeMaxDynamicSharedMemorySize,
                         FLASH_SMEM);

    // 0) fused prepass: fp32 -> fp16 (grid-stride, MLP~4)
    cvt_all<<<640, 256>>>(x, Wqkv, out_w, xh, wqkvh, wouth);

    // 1) QKV projection -> fp16 qkv   [2048,2048]@[2048,6144]
    gemm_h<<<dim3(QKV_N / 128, SEQ / 256), 512, GEMM_SMEM>>>(
        xh, wqkvh, Wqkv_bias, qkv, nullptr, SEQ, QKV_N, DMODEL);

    // 2) Variable split-KV flash attention (chunk=4) -> partials / direct attn
    flash_split<<<dim3(NITEMS, NH), 256, FLASH_SMEM>>>(qkv, attn_bias, opart, oml, attn);

    // 2b) combine partials -> fp16 attn (rows 256.. only)
    combineN<<<SEQ - 256, 256>>>(opart, oml, attn);

    // 3) Output projection -> fp32 out   [2048,2048]@[2048,2048]
    gemm_h<<<dim3(DMODEL / 128, SEQ / 256), 512, GEMM_SMEM>>>(
        attn, wouth, out_b, nullptr, out, SEQ, DMODEL, DMODEL);
}

// round 17
// speedup vs baseline: 1.0100x; 1.0100x over previous
#include <cuda_runtime.h>
#include <cuda_fp16.h>
#include <math.h>
#include <stdint.h>

#define SEQ    2048
#define DMODEL 2048
#define NH     16
#define DH     128
#define QKV_N  6144
#define NQB    (SEQ / 128)              // 16 q-tiles
#define MAXSPL 8
#define NITEMS 72                       // sum of ns(qb) = (2qb+5)/4 over qb=0..15

// ---------------------------------------------------------------------------
// Scratch (__device__ globals; allocation-free rule)
// ---------------------------------------------------------------------------
__device__ __align__(16) __half g_xh[SEQ * DMODEL];
__device__ __align__(16) __half g_wqkvh[(size_t)DMODEL * QKV_N];   // [K][N] fp16
__device__ __align__(16) __half g_wouth[(size_t)DMODEL * DMODEL];  // [K][N] fp16
__device__ __align__(16) __half g_qkv[(size_t)SEQ * QKV_N];
__device__ __align__(16) __half g_attn[SEQ * DMODEL];
__device__ __align__(16) __half g_opart[(size_t)MAXSPL * SEQ * DMODEL]; // normalized fp16 partials
__device__ __align__(16) float  g_oml[MAXSPL * SEQ * NH * 2];           // (m, l)

// ---------------------------------------------------------------------------
// PTX helpers
// ---------------------------------------------------------------------------
__device__ __forceinline__ uint32_t smem_u32(const void* p) {
    uint32_t a;
    asm("{ .reg .u64 t; cvta.to.shared.u64 t, %1; cvt.u32.u64 %0, t; }"
        : "=r"(a) : "l"(p));
    return a;
}
__device__ __forceinline__ void ldmx4(uint32_t r[4], uint32_t addr) {
    asm volatile("ldmatrix.sync.aligned.m8n8.x4.shared.b16 {%0,%1,%2,%3}, [%4];"
                 : "=r"(r[0]), "=r"(r[1]), "=r"(r[2]), "=r"(r[3]) : "r"(addr));
}
__device__ __forceinline__ void ldmx4t(uint32_t r[4], uint32_t addr) {
    asm volatile("ldmatrix.sync.aligned.m8n8.x4.trans.shared.b16 {%0,%1,%2,%3}, [%4];"
                 : "=r"(r[0]), "=r"(r[1]), "=r"(r[2]), "=r"(r[3]) : "r"(addr));
}
__device__ __forceinline__ void mma_f16(float c[4], const uint32_t a[4],
                                        uint32_t b0, uint32_t b1) {
    asm volatile(
        "mma.sync.aligned.m16n8k16.row.col.f32.f16.f16.f32 "
        "{%0,%1,%2,%3}, {%4,%5,%6,%7}, {%8,%9}, {%0,%1,%2,%3};"
        : "+f"(c[0]), "+f"(c[1]), "+f"(c[2]), "+f"(c[3])
        : "r"(a[0]), "r"(a[1]), "r"(a[2]), "r"(a[3]), "r"(b0), "r"(b1));
}
__device__ __forceinline__ void cp16(uint32_t dst, const void* src) {
    asm volatile("cp.async.cg.shared.global [%0], [%1], 16;" :: "r"(dst), "l"(src));
}
#define CP_COMMIT() asm volatile("cp.async.commit_group;" ::: "memory")
#define CP_WAIT0()  asm volatile("cp.async.wait_group 0;" ::: "memory")
#define CP_WAIT1()  asm volatile("cp.async.wait_group 1;" ::: "memory")

__device__ __forceinline__ uint32_t packh2(float a, float b) {
    __half2 h = __floats2half2_rn(a, b);
    return *reinterpret_cast<uint32_t*>(&h);
}

// ---------------------------------------------------------------------------
// Prepass: fp32 -> fp16 for x and Wqkv only (out_w converted inside combineN).
// ---------------------------------------------------------------------------
#define S0 ((size_t)SEQ * DMODEL)
#define S1 ((size_t)DMODEL * QKV_N)
#define S2 ((size_t)DMODEL * DMODEL)

__global__ void cvt_xw(const float* __restrict__ x, const float* __restrict__ w1,
                       __half* __restrict__ xh, __half* __restrict__ w1h) {
    size_t i = ((size_t)blockIdx.x * 256 + threadIdx.x) * 4;
    const float* src; __half* dst; size_t off;
    if (i < S0) { src = x;  dst = xh;  off = i; }
    else        { src = w1; dst = w1h; off = i - S0; }
    float4 v = *reinterpret_cast<const float4*>(src + off);
    uint2 o;
    o.x = packh2(v.x, v.y);
    o.y = packh2(v.z, v.w);
    *reinterpret_cast<uint2*>(dst + off) = o;
}

// ---------------------------------------------------------------------------
// fp16 tensor GEMM (R12 winner): C[M,N] = A[M,K] @ B[K,N] + bias (B row-major)
// 256x128 CTA tile, BK=64, 512 threads (16 warps: 8m x 2n), warp tile 32x64.
// 3-stage cp.async pipeline (prefetch distance 2), one __syncthreads per tile.
// ---------------------------------------------------------------------------
#define BKH 64
#define A_PITCH_B 144
#define B_PITCH_B 272
#define A_TILE_B (256 * A_PITCH_B)      // 36864
#define B_TILE_B (64 * B_PITCH_B)       // 17408
#define STG_B (A_TILE_B + B_TILE_B)     // 54272
#define GEMM_SMEM (3 * STG_B)           // 162816

__global__ __launch_bounds__(512, 1) void gemm_h(
    const __half* __restrict__ A, const __half* __restrict__ B,
    const float* __restrict__ bias, __half* __restrict__ Ch,
    float* __restrict__ Cf, int M, int N, int K)
{
    extern __shared__ char sh[];
    const uint32_t sbase = smem_u32(sh);

    const int tid  = threadIdx.x;
    const int warp = tid >> 5;
    const int lane = tid & 31;
    const int gq   = lane >> 2;
    const int kq   = lane & 3;
    const int wm   = warp >> 1;
    const int wn   = warp & 1;
    const int row0 = blockIdx.y * 256;
    const int col0 = blockIdx.x * 128;
    const int ntiles = K / BKH;

    const int lrA = tid >> 1;
    const int lbA = (tid & 1) * 64;
    const __half* gA = A + (size_t)(row0 + lrA) * K + (lbA >> 1);
    const int brB = tid >> 3;
    const int bcB = (tid & 7) * 32;
    const __half* gB = B + (size_t)brB * N + col0 + (bcB >> 1);

    const uint32_t aRel = (uint32_t)((wm * 32 + (lane & 15)) * A_PITCH_B
                                     + (lane >> 4) * 16);
    const uint32_t bRel = (uint32_t)A_TILE_B
        + (uint32_t)(((lane & 7) + ((lane >> 3) & 1) * 8) * B_PITCH_B
                     + ((lane >> 4) & 1) * 16 + wn * 128);

    float acc[2][8][4];
    #pragma unroll
    for (int mt = 0; mt < 2; mt++)
        #pragma unroll
        for (int nt = 0; nt < 8; nt++)
            #pragma unroll
            for (int i = 0; i < 4; i++) acc[mt][nt][i] = 0.f;

    #define LOAD_TILE(t, s) do {                                                \
        uint32_t base_ = sbase + (uint32_t)(s) * STG_B;                         \
        const __half* a_ = gA + (size_t)(t) * BKH;                              \
        uint32_t da_ = base_ + (uint32_t)(lrA * A_PITCH_B + lbA);               \
        cp16(da_,      a_);      cp16(da_ + 16, a_ + 8);                        \
        cp16(da_ + 32, a_ + 16); cp16(da_ + 48, a_ + 24);                       \
        const __half* b_ = gB + (size_t)(t) * BKH * N;                          \
        uint32_t db_ = base_ + A_TILE_B + (uint32_t)(brB * B_PITCH_B + bcB);    \
        cp16(db_, b_); cp16(db_ + 16, b_ + 8);                                  \
        CP_COMMIT();                                                            \
    } while (0)

    #define COMPUTE(s) do {                                                     \
        uint32_t ab_ = sbase + (uint32_t)(s) * STG_B + aRel;                    \
        uint32_t bb_ = sbase + (uint32_t)(s) * STG_B + bRel;                    \
        _Pragma("unroll")                                                       \
        for (int ks = 0; ks < 4; ks++) {                                        \
            uint32_t af0[4], af1[4];                                            \
            ldmx4(af0, ab_ + ks * 32);                                          \
            ldmx4(af1, ab_ + 16 * A_PITCH_B + ks * 32);                         \
            _Pragma("unroll")                                                   \
            for (int p = 0; p < 4; p++) {                                       \
                uint32_t bf[4];                                                 \
                ldmx4t(bf, bb_ + ks * (16 * B_PITCH_B) + p * 32);               \
                mma_f16(acc[0][2 * p],     af0, bf[0], bf[1]);                  \
                mma_f16(acc[0][2 * p + 1], af0, bf[2], bf[3]);                  \
                mma_f16(acc[1][2 * p],     af1, bf[0], bf[1]);                  \
                mma_f16(acc[1][2 * p + 1], af1, bf[2], bf[3]);                  \
            }                                                                   \
        }                                                                       \
    } while (0)

    LOAD_TILE(0, 0);
    LOAD_TILE(1, 1);
    for (int t = 0; t < ntiles; t++) {
        if (t + 1 < ntiles) CP_WAIT1(); else CP_WAIT0();
        __syncthreads();
        if (t + 2 < ntiles) {
            int s2 = (t + 2) % 3;
            LOAD_TILE(t + 2, s2);
        }
        COMPUTE(t % 3);
    }

    #pragma unroll
    for (int mt = 0; mt < 2; mt++) {
        int r = row0 + wm * 32 + mt * 16 + gq;
        #pragma unroll
        for (int nt = 0; nt < 8; nt++) {
            int c = col0 + wn * 64 + nt * 8 + kq * 2;
            float b0 = bias[c], b1 = bias[c + 1];
            float v0 = acc[mt][nt][0] + b0, v1 = acc[mt][nt][1] + b1;
            float v2 = acc[mt][nt][2] + b0, v3 = acc[mt][nt][3] + b1;
            if (Ch) {
                *reinterpret_cast<uint32_t*>(&Ch[(size_t)r * N + c]) = packh2(v0, v1);
                *reinterpret_cast<uint32_t*>(&Ch[(size_t)(r + 8) * N + c]) = packh2(v2, v3);
            } else {
                *reinterpret_cast<float2*>(&Cf[(size_t)r * N + c]) = make_float2(v0, v1);
                *reinterpret_cast<float2*>(&Cf[(size_t)(r + 8) * N + c]) = make_float2(v2, v3);
            }
        }
    }
}

// ---------------------------------------------------------------------------
// Variable split-KV flash attention, chunk = 4 key-blocks per CTA (R14 exact).
// ns==1 (qb<=1): writes final normalized output DIRECTLY to attn.
// ns>1: writes NORMALIZED fp16 partial O + (m, l) fp32; combineN merges.
// ---------------------------------------------------------------------------
#define FROW_B 272
#define QTILE_B (128 * FROW_B)          // 34816
#define KTILE_B (64 * FROW_B)           // 17408
#define KVSTG_B (2 * KTILE_B)           // 34816
#define FLASH_SMEM (QTILE_B + 2 * KVSTG_B)  // 104448

__global__ __launch_bounds__(256, 2) void flash_split(
    const __half* __restrict__ qkv, const float* __restrict__ attn_bias,
    __half* __restrict__ Opart, float* __restrict__ Oml,
    __half* __restrict__ attn)
{
    extern __shared__ char fsm[];
    const uint32_t qsb  = smem_u32(fsm);
    const uint32_t kvsb = qsb + QTILE_B;

    // item -> (qb, split), heavy-first (qb 15 down)
    int item = blockIdx.x;
    int qb = NQB - 1, split = 0;
    #pragma unroll
    for (int it = 0; it < NQB; it++) {
        int ns_ = (2 * qb + 5) >> 2;
        if (item < ns_) { split = item; break; }
        item -= ns_; qb--;
    }
    const int ns  = (2 * qb + 5) >> 2;

    const int nb  = 2 * qb + 2;                // total causal key blocks
    const int kb0 = split * 4;
    int kend = kb0 + 4; if (kend > nb) kend = nb;
    const int nkb = kend - kb0;

    const int h    = blockIdx.y;
    const int tid  = threadIdx.x;
    const int warp = tid >> 5;
    const int lane = tid & 31;
    const int gq   = lane >> 2;
    const int kq   = lane & 3;

    const float scale = 0.08838834764831845f;  // 1/sqrt(128)
    const float* bh = attn_bias + (size_t)h * SEQ;

    const uint32_t qOff = qsb + (uint32_t)((warp * 16 + (lane & 15)) * FROW_B
                                           + (lane >> 4) * 16);
    const int kRow = (lane & 7) + ((lane >> 4) & 1) * 8;
    const uint32_t kRel = (uint32_t)(kRow * FROW_B + ((lane >> 3) & 1) * 16);
    const int vRow = (lane & 7) + ((lane >> 3) & 1) * 8;
    const uint32_t vRel = (uint32_t)(vRow * FROW_B + ((lane >> 4) & 1) * 16) + KTILE_B;

    #define LOADKV(kbg_, s_) do {                                               \
        uint32_t kvb_ = kvsb + (uint32_t)(s_) * KVSTG_B;                        \
        _Pragma("unroll")                                                       \
        for (int i_ = 0; i_ < 4; i_++) {                                        \
            int idx_ = tid + i_ * 256;                                          \
            int r_ = idx_ >> 4, c_ = idx_ & 15;                                 \
            const __half* kp_ = &qkv[(size_t)((kbg_) * 64 + r_) * QKV_N         \
                                     + DMODEL + h * DH + c_ * 8];               \
            uint32_t d_ = kvb_ + (uint32_t)(r_ * FROW_B + c_ * 16);             \
            cp16(d_, kp_);                                                      \
            cp16(d_ + KTILE_B, kp_ + DMODEL);                                   \
        }                                                                       \
        CP_COMMIT();                                                            \
    } while (0)

    // ---- prologue: Q tile + first K/V block ----
    #pragma unroll
    for (int i = 0; i < 8; i++) {
        int idx = tid + i * 256;
        int r = idx >> 4, c = idx & 15;
        cp16(qsb + (uint32_t)(r * FROW_B + c * 16),
             &qkv[(size_t)(qb * 128 + r) * QKV_N + h * DH + c * 8]);
    }
    LOADKV(kb0, 0);

    float o[16][4];
    #pragma unroll
    for (int nt = 0; nt < 16; nt++)
        #pragma unroll
        for (int i = 0; i < 4; i++) o[nt][i] = 0.f;
    float m0 = -1e30f, m1 = -1e30f, l0 = 0.f, l1 = 0.f;

    const int qrow0 = qb * 128 + warp * 16 + gq;

    for (int kb = 0; kb < nkb; kb++) {
        const int kbg = kb0 + kb;
        CP_WAIT0();
        __syncthreads();
        if (kb + 1 < nkb) LOADKV(kb0 + kb + 1, (kb + 1) & 1);

        const uint32_t stg = kvsb + (uint32_t)(kb & 1) * KVSTG_B;
        const uint32_t kOff = stg + kRel;
        const uint32_t vOff = stg + vRel;

        // ---- S(16x64) = Q @ K^T ----
        float s[8][4];
        #pragma unroll
        for (int nt = 0; nt < 8; nt++)
            #pragma unroll
            for (int i = 0; i < 4; i++) s[nt][i] = 0.f;

        #pragma unroll
        for (int ks = 0; ks < 8; ks++) {
            uint32_t aq[4];
            ldmx4(aq, qOff + ks * 32);
            #pragma unroll
            for (int p = 0; p < 4; p++) {
                uint32_t bf[4];
                ldmx4(bf, kOff + p * (16 * FROW_B) + ks * 32);
                mma_f16(s[2 * p],     aq, bf[0], bf[1]);
                mma_f16(s[2 * p + 1], aq, bf[2], bf[3]);
            }
        }

        // ---- bias + scale + causal mask ----
        const bool diag = (kbg >= 2 * qb);
        #pragma unroll
        for (int nt = 0; nt < 8; nt++) {
            int j = nt * 8 + kq * 2;
            float b0v = bh[kbg * 64 + j], b1v = bh[kbg * 64 + j + 1];
            s[nt][0] = s[nt][0] * scale + b0v;
            s[nt][1] = s[nt][1] * scale + b1v;
            s[nt][2] = s[nt][2] * scale + b0v;
            s[nt][3] = s[nt][3] * scale + b1v;
            if (diag) {
                int jg = kbg * 64 + j;
                if (jg     > qrow0)     s[nt][0] = -1e30f;
                if (jg + 1 > qrow0)     s[nt][1] = -1e30f;
                if (jg     > qrow0 + 8) s[nt][2] = -1e30f;
                if (jg + 1 > qrow0 + 8) s[nt][3] = -1e30f;
            }
        }

        // ---- online softmax (guarded exp: all-masked rows stay zero) ----
        float mx0 = -1e30f, mx1 = -1e30f;
        #pragma unroll
        for (int nt = 0; nt < 8; nt++) {
            mx0 = fmaxf(mx0, fmaxf(s[nt][0], s[nt][1]));
            mx1 = fmaxf(mx1, fmaxf(s[nt][2], s[nt][3]));
        }
        mx0 = fmaxf(mx0, __shfl_xor_sync(0xffffffffu, mx0, 1));
        mx0 = fmaxf(mx0, __shfl_xor_sync(0xffffffffu, mx0, 2));
        mx1 = fmaxf(mx1, __shfl_xor_sync(0xffffffffu, mx1, 1));
        mx1 = fmaxf(mx1, __shfl_xor_sync(0xffffffffu, mx1, 2));

        float mn0 = fmaxf(m0, mx0), mn1 = fmaxf(m1, mx1);
        float al0 = __expf(m0 - mn0), al1 = __expf(m1 - mn1);
        m0 = mn0; m1 = mn1;

        float ps0 = 0.f, ps1 = 0.f;
        #pragma unroll
        for (int nt = 0; nt < 8; nt++) {
            s[nt][0] = (s[nt][0] > -1e29f) ? __expf(s[nt][0] - mn0) : 0.f;
            s[nt][1] = (s[nt][1] > -1e29f) ? __expf(s[nt][1] - mn0) : 0.f;
            s[nt][2] = (s[nt][2] > -1e29f) ? __expf(s[nt][2] - mn1) : 0.f;
            s[nt][3] = (s[nt][3] > -1e29f) ? __expf(s[nt][3] - mn1) : 0.f;
            ps0 += s[nt][0] + s[nt][1];
            ps1 += s[nt][2] + s[nt][3];
        }
        ps0 += __shfl_xor_sync(0xffffffffu, ps0, 1);
        ps0 += __shfl_xor_sync(0xffffffffu, ps0, 2);
        ps1 += __shfl_xor_sync(0xffffffffu, ps1, 1);
        ps1 += __shfl_xor_sync(0xffffffffu, ps1, 2);
        l0 = l0 * al0 + ps0;
        l1 = l1 * al1 + ps1;

        #pragma unroll
        for (int nt = 0; nt < 16; nt++) {
            o[nt][0] *= al0; o[nt][1] *= al0;
            o[nt][2] *= al1; o[nt][3] *= al1;
        }

        // ---- O += P @ V (P straight from registers) ----
        #pragma unroll
        for (int ks = 0; ks < 4; ks++) {
            uint32_t ap[4];
            ap[0] = packh2(s[2 * ks][0],     s[2 * ks][1]);
            ap[1] = packh2(s[2 * ks][2],     s[2 * ks][3]);
            ap[2] = packh2(s[2 * ks + 1][0], s[2 * ks + 1][1]);
            ap[3] = packh2(s[2 * ks + 1][2], s[2 * ks + 1][3]);
            #pragma unroll
            for (int p = 0; p < 8; p++) {
                uint32_t bf[4];
                ldmx4t(bf, vOff + ks * (16 * FROW_B) + p * 32);
                mma_f16(o[2 * p],     ap, bf[0], bf[1]);
                mma_f16(o[2 * p + 1], ap, bf[2], bf[3]);
            }
        }
    }

    // ---- epilogue: normalized fp16; direct to attn when ns==1 ----
    float il0 = (l0 > 0.f) ? 1.f / l0 : 0.f;
    float il1 = (l1 > 0.f) ? 1.f / l1 : 0.f;
    int r = qrow0;
    __half* op = (ns == 1)
        ? attn  + (size_t)r * DMODEL + h * DH
        : Opart + (size_t)(split * SEQ + r) * DMODEL + h * DH;
    #pragma unroll
    for (int nt = 0; nt < 16; nt++) {
        int col = nt * 8 + kq * 2;
        *reinterpret_cast<uint32_t*>(op + col) =
            packh2(o[nt][0] * il0, o[nt][1] * il0);
        *reinterpret_cast<uint32_t*>(op + 8 * DMODEL + col) =
            packh2(o[nt][2] * il1, o[nt][3] * il1);
    }
    if (ns > 1 && kq == 0) {
        float* ml = Oml + ((size_t)(split * SEQ + r) * NH + h) * 2;
        ml[0] = m0; ml[1] = l0;
        float* ml8 = Oml + ((size_t)(split * SEQ + r + 8) * NH + h) * 2;
        ml8[0] = m1; ml8[1] = l1;
    }
}

// ---------------------------------------------------------------------------
// Combine ns(qb) normalized fp16 partials -> fp16 attn (rows 256..2047),
// PLUS out_w fp32->fp16 conversion in extra blocks (overlapped, both
// bandwidth-bound). Blocks [0, 1792): combine; blocks [1792, 2304): convert.
// ---------------------------------------------------------------------------
#define CMB_BLOCKS (SEQ - 256)          // 1792
#define W2_BLOCKS  512                  // 512*256*8 float4 = S2 floats

__global__ void combineN(const __half* __restrict__ Opart,
                         const float* __restrict__ Oml,
                         __half* __restrict__ attn,
                         const float* __restrict__ w2,
                         __half* __restrict__ w2h)
{
    __shared__ float2 sml[MAXSPL][NH];

    if (blockIdx.x >= CMB_BLOCKS) {
        // ---- out_w conversion lane ----
        int b = blockIdx.x - CMB_BLOCKS;
        size_t base = ((size_t)b * 256 + threadIdx.x) * 4;
        #pragma unroll
        for (int it = 0; it < 8; it++) {
            size_t i = base + (size_t)it * (W2_BLOCKS * 256 * 4);
            float4 v = *reinterpret_cast<const float4*>(w2 + i);
            uint2 o;
            o.x = packh2(v.x, v.y);
            o.y = packh2(v.z, v.w);
            *reinterpret_cast<uint2*>(w2h + i) = o;
        }
        return;
    }

    int r = blockIdx.x + 256;           // rows 0..255 (qb 0,1) handled by flash
    int t = threadIdx.x;
    int c0 = t * 8;
    int h = c0 >> 7;
    int qb = r >> 7;
    int ns = (2 * qb + 5) >> 2;

    if (t < ns * NH) {
        int s = t >> 4, hh = t & 15;
        sml[s][hh] = *reinterpret_cast<const float2*>(
            Oml + ((size_t)(s * SEQ + r) * NH + hh) * 2);
    }
    __syncthreads();

    float m = -1e30f;
    #pragma unroll
    for (int s = 0; s < MAXSPL; s++) {
        if (s >= ns) break;
        m = fmaxf(m, sml[s][h].x);
    }
    float L = 0.f;
    float al[MAXSPL];
    #pragma unroll
    for (int s = 0; s < MAXSPL; s++) {
        if (s >= ns) break;
        al[s] = sml[s][h].y * __expf(sml[s][h].x - m);
        L += al[s];
    }
    float inv = 1.f / L;

    float a[8] = {0.f, 0.f, 0.f, 0.f, 0.f, 0.f, 0.f, 0.f};
    #pragma unroll
    for (int s = 0; s < MAXSPL; s++) {
        if (s >= ns) break;
        float w = al[s];
        const __half* p = Opart + (size_t)(s * SEQ + r) * DMODEL + c0;
        uint4 v = *reinterpret_cast<const uint4*>(p);
        const __half2* h2 = reinterpret_cast<const __half2*>(&v);
        #pragma unroll
        for (int q = 0; q < 4; q++) {
            float2 f = __half22float2(h2[q]);
            a[2 * q]     += w * f.x;
            a[2 * q + 1] += w * f.y;
        }
    }

    uint4 outv;
    outv.x = packh2(a[0] * inv, a[1] * inv);
    outv.y = packh2(a[2] * inv, a[3] * inv);
    outv.z = packh2(a[4] * inv, a[5] * inv);
    outv.w = packh2(a[6] * inv, a[7] * inv);
    *reinterpret_cast<uint4*>(attn + (size_t)r * DMODEL + c0) = outv;
}

// ---------------------------------------------------------------------------
// kernel_launch
// ---------------------------------------------------------------------------
extern "C" void kernel_launch(void* const* d_in, const int* in_sizes, int n_in,
                              void* d_out, int out_size)
{
    (void)in_sizes; (void)n_in; (void)out_size;
    const float* x         = (const float*)d_in[0];
    const float* Wqkv      = (const float*)d_in[1];
    const float* Wqkv_bias = (const float*)d_in[2];
    const float* out_w     = (const float*)d_in[3];
    const float* out_b     = (const float*)d_in[4];
    const float* attn_bias = (const float*)d_in[5];
    float* out = (float*)d_out;

    __half *xh, *wqkvh, *wouth, *qkv, *attn, *opart;
    float *oml;
    cudaGetSymbolAddress((void**)&xh,    g_xh);
    cudaGetSymbolAddress((void**)&wqkvh, g_wqkvh);
    cudaGetSymbolAddress((void**)&wouth, g_wouth);
    cudaGetSymbolAddress((void**)&qkv,   g_qkv);
    cudaGetSymbolAddress((void**)&attn,  g_attn);
    cudaGetSymbolAddress((void**)&opart, g_opart);
    cudaGetSymbolAddress((void**)&oml,   g_oml);

    cudaFuncSetAttribute(gemm_h, cudaFuncAttributeMaxDynamicSharedMemorySize,
                         GEMM_SMEM);
    cudaFuncSetAttribute(flash_split, cudaFuncAttributeMaxDynamicSharedMemorySize,
                         FLASH_SMEM);

    // 0) prepass: fp32 -> fp16 for x + Wqkv (out_w handled in combineN)
    cvt_xw<<<(int)((S0 + S1) / 1024), 256>>>(x, Wqkv, xh, wqkvh);

    // 1) QKV projection -> fp16 qkv   [2048,2048]@[2048,6144]
    gemm_h<<<dim3(QKV_N / 128, SEQ / 256), 512, GEMM_SMEM>>>(
        xh, wqkvh, Wqkv_bias, qkv, nullptr, SEQ, QKV_N, DMODEL);

    // 2) Variable split-KV flash attention (chunk=4) -> partials / direct attn
    flash_split<<<dim3(NITEMS, NH), 256, FLASH_SMEM>>>(qkv, attn_bias, opart, oml, attn);

    // 2b) combine partials -> fp16 attn  +  out_w fp32->fp16 (overlapped)
    combineN<<<CMB_BLOCKS + W2_BLOCKS, 256>>>(opart, oml, attn, out_w, wouth);

    // 3) Output projection -> fp32 out   [2048,2048]@[2048,2048]
    gemm_h<<<dim3(DMODEL / 128, SEQ / 256), 512, GEMM_SMEM>>>(
        attn, wouth, out_b, nullptr, out, SEQ, DMODEL, DMODEL);
}